// round 3
// baseline (speedup 1.0000x reference)
#include <cuda_runtime.h>
#include <cuda_bf16.h>
#include <stdint.h>

#define DI __device__ __forceinline__

// ---------------- problem constants ----------------
static constexpr int    NDIM     = 4096;
static constexpr float  INVSCALE = 1.0f / (31.75f * 127.0f);   // 1/(sx*sw)

// ---------------- GEMM tiling (int8) ----------------
static constexpr int BM = 128, BN = 128, BK = 64;       // BK in int8 elems (64 B rows)
static constexpr int STAGES = 4;
static constexpr int KT = NDIM / BK;                    // 64 k-iterations
static constexpr int A_STAGE_B = BM * BK;               // 8192 B
static constexpr int B_STAGE_B = BN * BK;               // 8192 B
static constexpr int STAGE_B   = A_STAGE_B + B_STAGE_B; // 16384 B
static constexpr int SMEM_TOTAL = STAGES * STAGE_B;     // 65536 B

// ---------------- device scratch (allocation-free rule) ----------------
__device__ int8_t g_Xq[(size_t)NDIM * NDIM];   // quantized activations (int8)
__device__ int8_t g_Wq[(size_t)NDIM * NDIM];   // quantized weights (int8)
__device__ float  g_badd[NDIM];                // epilogue bias term

// ---------------- PTX helpers ----------------
DI uint32_t smem_u32(const void* p) {
    uint32_t a;
    asm("{ .reg .u64 t; cvta.to.shared.u64 t, %1; cvt.u32.u64 %0, t; }" : "=r"(a) : "l"(p));
    return a;
}
DI void cp16(uint32_t dst, const void* src) {
    asm volatile("cp.async.cg.shared.global [%0], [%1], 16;" :: "r"(dst), "l"(src) : "memory");
}
DI void cp_commit() { asm volatile("cp.async.commit_group;" ::: "memory"); }
template <int N> DI void cp_wait() { asm volatile("cp.async.wait_group %0;" :: "n"(N) : "memory"); }

DI void ldsm4(uint32_t (&r)[4], uint32_t addr) {
    asm volatile("ldmatrix.sync.aligned.m8n8.x4.shared.b16 {%0,%1,%2,%3}, [%4];"
                 : "=r"(r[0]), "=r"(r[1]), "=r"(r[2]), "=r"(r[3]) : "r"(addr));
}
DI void imma16832(int* c, const uint32_t* a, uint32_t b0, uint32_t b1) {
    asm volatile(
        "mma.sync.aligned.m16n8k32.row.col.s32.s8.s8.s32 "
        "{%0,%1,%2,%3}, {%4,%5,%6,%7}, {%8,%9}, {%0,%1,%2,%3};"
        : "+r"(c[0]), "+r"(c[1]), "+r"(c[2]), "+r"(c[3])
        : "r"(a[0]), "r"(a[1]), "r"(a[2]), "r"(a[3]), "r"(b0), "r"(b1));
}

// swizzled byte offset for (row, 16B-chunk c in [0,4)) within a [rows x 64B] tile
DI uint32_t sw_off(int row, int c) {
    return (uint32_t)(row * 64 + ((c ^ ((row >> 1) & 3)) << 4));
}

// ---------------- quantize kernels ----------------
// each thread: 16 floats -> 16 int8 (one uint4 store)
__global__ void quant_kernel(const float4* __restrict__ src, int which,
                             float clip, float scale) {
    size_t i = (size_t)blockIdx.x * blockDim.x + threadIdx.x;
    uint32_t words[4];
#pragma unroll
    for (int j = 0; j < 4; ++j) {
        float4 v = src[i * 4 + j];
        int q0 = __float2int_rn(fminf(clip, fmaxf(-clip, v.x)) * scale);
        int q1 = __float2int_rn(fminf(clip, fmaxf(-clip, v.y)) * scale);
        int q2 = __float2int_rn(fminf(clip, fmaxf(-clip, v.z)) * scale);
        int q3 = __float2int_rn(fminf(clip, fmaxf(-clip, v.w)) * scale);
        words[j] = (uint32_t)(q0 & 0xFF) | ((uint32_t)(q1 & 0xFF) << 8) |
                   ((uint32_t)(q2 & 0xFF) << 16) | ((uint32_t)(q3 & 0xFF) << 24);
    }
    uint4 o = make_uint4(words[0], words[1], words[2], words[3]);
    uint4* dst = reinterpret_cast<uint4*>(which ? g_Wq : g_Xq);
    dst[i] = o;
}

__global__ void quant_bias_kernel(const float* __restrict__ b) {
    int i = blockIdx.x * blockDim.x + threadIdx.x;
    float q = rintf(fminf(1.0f, fmaxf(-1.0f, b[i])) * 127.0f);
    g_badd[i] = 32.0f * q * INVSCALE;   // quantized ones-column (=32) * quantized bias
}

// ---------------- GEMM ----------------
DI void load_stage(const int8_t* __restrict__ Ag,
                   const int8_t* __restrict__ Bg,
                   uint32_t a_s, uint32_t b_s, int kc, int tid) {
    // A: 128 rows x 4 chunks (16B); 256 threads x 2
#pragma unroll
    for (int j = 0; j < 2; ++j) {
        int idx = tid + j * 256;
        int row = idx >> 2, c = idx & 3;
        cp16(a_s + sw_off(row, c), Ag + ((size_t)row * NDIM + kc + c * 16));
    }
#pragma unroll
    for (int j = 0; j < 2; ++j) {
        int idx = tid + j * 256;
        int row = idx >> 2, c = idx & 3;
        cp16(b_s + sw_off(row, c), Bg + ((size_t)row * NDIM + kc + c * 16));
    }
}

__global__ __launch_bounds__(256, 2)
void gemm_kernel(const float* __restrict__ noise, float* __restrict__ out) {
    extern __shared__ __align__(1024) char smem[];
    const uint32_t smem_base = smem_u32(smem);
    const int tid  = threadIdx.x;
    const int lane = tid & 31;
    const int warp = tid >> 5;
    const int warpM = warp >> 1;     // 0..3, 32 rows each
    const int warpN = warp & 1;      // 0..1, 64 cols each

    const int tileM = blockIdx.y, tileN = blockIdx.x;
    const int8_t* Ag = g_Xq + (size_t)tileM * BM * NDIM;
    const int8_t* Bg = g_Wq + (size_t)tileN * BN * NDIM;

    int c[2][8][4];
#pragma unroll
    for (int i = 0; i < 2; ++i)
#pragma unroll
        for (int j = 0; j < 8; ++j)
#pragma unroll
            for (int k = 0; k < 4; ++k) c[i][j][k] = 0;

    // ---- precompute per-lane swizzled in-stage ldmatrix offsets ----
    // A (m16n8k32 s8 A frag via ldsm.x4): lanes0-15 -> rows 0-15 chunk 2kk,
    //                                     lanes16-31 -> rows 0-15 chunk 2kk+1
    uint32_t offA[2][2];   // [half m16][kk]
    {
        const int cbit = lane >> 4;
#pragma unroll
        for (int h = 0; h < 2; ++h) {
            const int row = warpM * 32 + h * 16 + (lane & 15);
#pragma unroll
            for (int kk = 0; kk < 2; ++kk)
                offA[h][kk] = sw_off(row, (kk << 1) | cbit);
        }
    }
    // B: one ldsm.x4 covers two n8 blocks (16 n-rows):
    //   lanes0-7:  rows +0..7  chunk 2kk      -> r0 = b0 (low n8)
    //   lanes8-15: rows +0..7  chunk 2kk+1    -> r1 = b1 (low n8)
    //   lanes16-23: rows +8..15 chunk 2kk     -> r2 = b0 (high n8)
    //   lanes24-31: rows +8..15 chunk 2kk+1   -> r3 = b1 (high n8)
    uint32_t offB[4][2];   // [n16 block q][kk]
    {
        const int rl = (lane & 7) + ((lane >> 4) << 3);
        const int cbit = (lane >> 3) & 1;
#pragma unroll
        for (int q = 0; q < 4; ++q) {
            const int row = warpN * 64 + q * 16 + rl;
#pragma unroll
            for (int kk = 0; kk < 2; ++kk)
                offB[q][kk] = sw_off(row, (kk << 1) | cbit);
        }
    }

    // prologue: fill STAGES-1 stages
#pragma unroll
    for (int s = 0; s < STAGES - 1; ++s) {
        uint32_t a_s = smem_base + s * STAGE_B;
        load_stage(Ag, Bg, a_s, a_s + A_STAGE_B, s * BK, tid);
        cp_commit();
    }

    for (int kt = 0; kt < KT; ++kt) {
        cp_wait<STAGES - 2>();
        __syncthreads();
        const int s = kt & (STAGES - 1);
        const uint32_t a_s = smem_base + s * STAGE_B;
        const uint32_t b_s = a_s + A_STAGE_B;

        if (kt + STAGES - 1 < KT) {
            uint32_t na = smem_base + ((kt + STAGES - 1) & (STAGES - 1)) * STAGE_B;
            load_stage(Ag, Bg, na, na + A_STAGE_B, (kt + STAGES - 1) * BK, tid);
        }
        cp_commit();

#pragma unroll
        for (int kk = 0; kk < 2; ++kk) {
            uint32_t a0[4], a1[4], b[4][4];
            ldsm4(a0, a_s + offA[0][kk]);
            ldsm4(a1, a_s + offA[1][kk]);
#pragma unroll
            for (int q = 0; q < 4; ++q) ldsm4(b[q], b_s + offB[q][kk]);
#pragma unroll
            for (int q = 0; q < 4; ++q) {
                imma16832(c[0][2 * q + 0], a0, b[q][0], b[q][1]);
                imma16832(c[0][2 * q + 1], a0, b[q][2], b[q][3]);
                imma16832(c[1][2 * q + 0], a1, b[q][0], b[q][1]);
                imma16832(c[1][2 * q + 1], a1, b[q][2], b[q][3]);
            }
        }
    }

    // ---- fused epilogue: out = acc*INV + badd[n] + 0.01*noise ----
    const int mBase = tileM * BM + warpM * 32 + (lane >> 2);
    const int nBase = tileN * BN + warpN * 64 + (lane & 3) * 2;
#pragma unroll
    for (int mt = 0; mt < 2; ++mt) {
#pragma unroll
        for (int nt = 0; nt < 8; ++nt) {
#pragma unroll
            for (int half = 0; half < 2; ++half) {
                const int m = mBase + mt * 16 + half * 8;
                const int n = nBase + nt * 8;
                const size_t off = (size_t)m * NDIM + n;
                float2 nz = *reinterpret_cast<const float2*>(noise + off);
                float2 bd = *reinterpret_cast<const float2*>(g_badd + n);
                float2 o;
                o.x = fmaf((float)c[mt][nt][2 * half + 0], INVSCALE, fmaf(0.01f, nz.x, bd.x));
                o.y = fmaf((float)c[mt][nt][2 * half + 1], INVSCALE, fmaf(0.01f, nz.y, bd.y));
                *reinterpret_cast<float2*>(out + off) = o;
            }
        }
    }
}

// ---------------- launch ----------------
extern "C" void kernel_launch(void* const* d_in, const int* in_sizes, int n_in,
                              void* d_out, int out_size) {
    const float* x  = (const float*)d_in[0];   // tensor  [4096,4096]
    const float* w  = (const float*)d_in[1];   // weights [4096,4096]
    const float* b  = (const float*)d_in[2];   // biases  [4096]
    const float* nz = (const float*)d_in[3];   // noise   [4096,4096]
    float* out = (float*)d_out;

    const int qgrid = (NDIM * NDIM / 16) / 256;  // 4096 blocks
    quant_kernel<<<qgrid, 256>>>((const float4*)x, 0, 4.0f, 31.75f);
    quant_kernel<<<qgrid, 256>>>((const float4*)w, 1, 1.0f, 127.0f);
    quant_bias_kernel<<<NDIM / 256, 256>>>(b);

    cudaFuncSetAttribute(gemm_kernel, cudaFuncAttributeMaxDynamicSharedMemorySize, SMEM_TOTAL);
    dim3 grid(NDIM / BN, NDIM / BM);            // 32 x 32 = 1024 CTAs
    gemm_kernel<<<grid, 256, SMEM_TOTAL>>>(nz, out);
}

// round 4
// speedup vs baseline: 1.3467x; 1.3467x over previous
#include <cuda_runtime.h>
#include <cuda_bf16.h>
#include <stdint.h>

#define DI __device__ __forceinline__

// ---------------- problem constants ----------------
static constexpr int    NDIM     = 4096;
static constexpr float  INVSCALE = 1.0f / (31.75f * 127.0f);   // 1/(sx*sw)

// ---------------- GEMM tiling (bf16 HMMA) ----------------
static constexpr int BM = 128, BN = 128, BK = 32;
static constexpr int STAGES = 5;
static constexpr int KT = NDIM / BK;                    // 128 k-iterations
static constexpr int A_STAGE_B = BM * BK * 2;           // 8192
static constexpr int B_STAGE_B = BN * BK * 2;           // 8192
static constexpr int STAGE_B   = A_STAGE_B + B_STAGE_B; // 16384
static constexpr int SMEM_TOTAL = STAGES * STAGE_B;     // 81920

// ---------------- device scratch (allocation-free rule) ----------------
__device__ __nv_bfloat16 g_Xq[(size_t)NDIM * NDIM];   // quantized activations (integer-valued bf16)
__device__ __nv_bfloat16 g_Wq[(size_t)NDIM * NDIM];   // quantized weights (integer-valued bf16)
__device__ float         g_badd[NDIM];                // epilogue bias term

// ---------------- PTX helpers ----------------
DI uint32_t smem_u32(const void* p) {
    uint32_t a;
    asm("{ .reg .u64 t; cvta.to.shared.u64 t, %1; cvt.u32.u64 %0, t; }" : "=r"(a) : "l"(p));
    return a;
}
DI void cp16(uint32_t dst, const void* src) {
    asm volatile("cp.async.cg.shared.global [%0], [%1], 16;" :: "r"(dst), "l"(src) : "memory");
}
DI void cp_commit() { asm volatile("cp.async.commit_group;" ::: "memory"); }
template <int N> DI void cp_wait() { asm volatile("cp.async.wait_group %0;" :: "n"(N) : "memory"); }

DI void ldsm4(uint32_t* r, uint32_t addr) {
    asm volatile("ldmatrix.sync.aligned.m8n8.x4.shared.b16 {%0,%1,%2,%3}, [%4];"
                 : "=r"(r[0]), "=r"(r[1]), "=r"(r[2]), "=r"(r[3]) : "r"(addr));
}
DI void mma16816(float* c, const uint32_t* a, uint32_t b0, uint32_t b1) {
    asm volatile(
        "mma.sync.aligned.m16n8k16.row.col.f32.bf16.bf16.f32 "
        "{%0,%1,%2,%3}, {%4,%5,%6,%7}, {%8,%9}, {%0,%1,%2,%3};"
        : "+f"(c[0]), "+f"(c[1]), "+f"(c[2]), "+f"(c[3])
        : "r"(a[0]), "r"(a[1]), "r"(a[2]), "r"(a[3]), "r"(b0), "r"(b1));
}

// swizzled byte offset for (row, 16B-chunk c in [0,4)) within a [rows x 32] bf16 tile
DI uint32_t sw_off(int row, int c) {
    return (uint32_t)(row * 64 + ((c ^ ((row >> 1) & 3)) << 4));
}

// ---------------- quantize kernels ----------------
__global__ void quant_kernel(const float4* __restrict__ src, int which,
                             float clip, float scale) {
    size_t i = (size_t)blockIdx.x * blockDim.x + threadIdx.x;
    float4 v = src[i];
    float a0 = rintf(fminf(clip, fmaxf(-clip, v.x)) * scale);
    float a1 = rintf(fminf(clip, fmaxf(-clip, v.y)) * scale);
    float a2 = rintf(fminf(clip, fmaxf(-clip, v.z)) * scale);
    float a3 = rintf(fminf(clip, fmaxf(-clip, v.w)) * scale);
    __nv_bfloat162 p0 = __floats2bfloat162_rn(a0, a1);
    __nv_bfloat162 p1 = __floats2bfloat162_rn(a2, a3);
    uint2 o;
    o.x = *reinterpret_cast<uint32_t*>(&p0);
    o.y = *reinterpret_cast<uint32_t*>(&p1);
    uint2* dst = reinterpret_cast<uint2*>(which ? g_Wq : g_Xq);
    dst[i] = o;
}

__global__ void quant_bias_kernel(const float* __restrict__ b) {
    int i = blockIdx.x * blockDim.x + threadIdx.x;
    float q = rintf(fminf(1.0f, fmaxf(-1.0f, b[i])) * 127.0f);
    g_badd[i] = 32.0f * q * INVSCALE;   // quantized ones-column (=32) * quantized bias
}

// ---------------- GEMM ----------------
DI void load_stage(const __nv_bfloat16* __restrict__ Ag,
                   const __nv_bfloat16* __restrict__ Bg,
                   uint32_t a_s, uint32_t b_s, int kc, int tid) {
#pragma unroll
    for (int j = 0; j < 2; ++j) {
        int idx = tid + j * 256;
        int row = idx >> 2, c = idx & 3;
        cp16(a_s + sw_off(row, c), Ag + ((size_t)row * NDIM + kc + c * 8));
    }
#pragma unroll
    for (int j = 0; j < 2; ++j) {
        int idx = tid + j * 256;
        int row = idx >> 2, c = idx & 3;
        cp16(b_s + sw_off(row, c), Bg + ((size_t)row * NDIM + kc + c * 8));
    }
}

__global__ __launch_bounds__(256, 2)
void gemm_kernel(const float* __restrict__ noise, float* __restrict__ out) {
    extern __shared__ __align__(1024) char smem[];
    const uint32_t smem_base = smem_u32(smem);
    const int tid  = threadIdx.x;
    const int lane = tid & 31;
    const int warp = tid >> 5;
    const int warpM = warp >> 1;     // 0..3, 32 rows each
    const int warpN = warp & 1;      // 0..1, 64 cols each

    const int tileM = blockIdx.y, tileN = blockIdx.x;
    const __nv_bfloat16* Ag = g_Xq + (size_t)tileM * BM * NDIM;
    const __nv_bfloat16* Bg = g_Wq + (size_t)tileN * BN * NDIM;

    float c[2][8][4];
#pragma unroll
    for (int i = 0; i < 2; ++i)
#pragma unroll
        for (int j = 0; j < 8; ++j)
#pragma unroll
            for (int k = 0; k < 4; ++k) c[i][j][k] = 0.0f;

    // ---- compressed per-lane swizzled ldmatrix offsets ----
    // swizzle pattern is invariant under row += 16, so only base offsets per kk needed.
    const int lrow = lane & 15;
    const int csel = lane >> 4;
    uint32_t offA0[2], offB0[2];   // [kk]
    {
        const int rA = warpM * 32 + lrow;
#pragma unroll
        for (int kk = 0; kk < 2; ++kk)
            offA0[kk] = sw_off(rA, (kk << 1) | csel);
        const int rB = warpN * 64 + lrow;
#pragma unroll
        for (int kk = 0; kk < 2; ++kk)
            offB0[kk] = sw_off(rB, (kk << 1) | csel);
    }

    // fragment double buffers: buf0 = even kk, buf1 = odd kk
    uint32_t afr[2][2][4];   // [buf][m-half][reg]
    uint32_t bfr[2][4][4];   // [buf][n16 block][reg]

    // prologue: fill STAGES-1 stages
#pragma unroll
    for (int s = 0; s < STAGES - 1; ++s) {
        uint32_t a_s = smem_base + s * STAGE_B;
        load_stage(Ag, Bg, a_s, a_s + A_STAGE_B, s * BK, tid);
        cp_commit();
    }

    int s = 0, s_next = 1, s_load = STAGES - 1;
    for (int kt = 0; kt < KT; ++kt) {
        cp_wait<STAGES - 3>();              // stages kt and kt+1 resident
        __syncthreads();
        const uint32_t a_s = smem_base + s * STAGE_B;
        const uint32_t b_s = a_s + A_STAGE_B;

        if (kt + STAGES - 1 < KT) {
            uint32_t na = smem_base + s_load * STAGE_B;
            load_stage(Ag, Bg, na, na + A_STAGE_B, (kt + STAGES - 1) * BK, tid);
        }
        cp_commit();

        if (kt == 0) {                      // bootstrap buf0 with kk=0 frags
            ldsm4(afr[0][0], a_s + offA0[0]);
            ldsm4(afr[0][1], a_s + offA0[0] + 1024);
#pragma unroll
            for (int q = 0; q < 4; ++q)
                ldsm4(bfr[0][q], b_s + offB0[0] + (uint32_t)(q * 1024));
        }

        // ---- kk = 0: prefetch kk=1 frags, compute on buf0 ----
        ldsm4(afr[1][0], a_s + offA0[1]);
        ldsm4(afr[1][1], a_s + offA0[1] + 1024);
#pragma unroll
        for (int q = 0; q < 4; ++q)
            ldsm4(bfr[1][q], b_s + offB0[1] + (uint32_t)(q * 1024));
#pragma unroll
        for (int q = 0; q < 4; ++q) {
            mma16816(c[0][2 * q + 0], afr[0][0], bfr[0][q][0], bfr[0][q][2]);
            mma16816(c[0][2 * q + 1], afr[0][0], bfr[0][q][1], bfr[0][q][3]);
            mma16816(c[1][2 * q + 0], afr[0][1], bfr[0][q][0], bfr[0][q][2]);
            mma16816(c[1][2 * q + 1], afr[0][1], bfr[0][q][1], bfr[0][q][3]);
        }

        // ---- kk = 1: prefetch next-iteration kk=0 frags, compute on buf1 ----
        if (kt + 1 < KT) {
            const uint32_t a_n = smem_base + s_next * STAGE_B;
            const uint32_t b_n = a_n + A_STAGE_B;
            ldsm4(afr[0][0], a_n + offA0[0]);
            ldsm4(afr[0][1], a_n + offA0[0] + 1024);
#pragma unroll
            for (int q = 0; q < 4; ++q)
                ldsm4(bfr[0][q], b_n + offB0[0] + (uint32_t)(q * 1024));
        }
#pragma unroll
        for (int q = 0; q < 4; ++q) {
            mma16816(c[0][2 * q + 0], afr[1][0], bfr[1][q][0], bfr[1][q][2]);
            mma16816(c[0][2 * q + 1], afr[1][0], bfr[1][q][1], bfr[1][q][3]);
            mma16816(c[1][2 * q + 0], afr[1][1], bfr[1][q][0], bfr[1][q][2]);
            mma16816(c[1][2 * q + 1], afr[1][1], bfr[1][q][1], bfr[1][q][3]);
        }

        if (++s == STAGES) s = 0;
        if (++s_next == STAGES) s_next = 0;
        if (++s_load == STAGES) s_load = 0;
    }

    // ---- fused epilogue: out = acc*INV + badd[n] + 0.01*noise ----
    const int mBase = tileM * BM + warpM * 32 + (lane >> 2);
    const int nBase = tileN * BN + warpN * 64 + (lane & 3) * 2;
#pragma unroll
    for (int mt = 0; mt < 2; ++mt) {
#pragma unroll
        for (int nt = 0; nt < 8; ++nt) {
#pragma unroll
            for (int half = 0; half < 2; ++half) {
                const int m = mBase + mt * 16 + half * 8;
                const int n = nBase + nt * 8;
                const size_t off = (size_t)m * NDIM + n;
                float2 nz = *reinterpret_cast<const float2*>(noise + off);
                float2 bd = *reinterpret_cast<const float2*>(g_badd + n);
                float2 o;
                o.x = fmaf(c[mt][nt][2 * half + 0], INVSCALE, fmaf(0.01f, nz.x, bd.x));
                o.y = fmaf(c[mt][nt][2 * half + 1], INVSCALE, fmaf(0.01f, nz.y, bd.y));
                *reinterpret_cast<float2*>(out + off) = o;
            }
        }
    }
}

// ---------------- launch ----------------
extern "C" void kernel_launch(void* const* d_in, const int* in_sizes, int n_in,
                              void* d_out, int out_size) {
    const float* x  = (const float*)d_in[0];   // tensor  [4096,4096]
    const float* w  = (const float*)d_in[1];   // weights [4096,4096]
    const float* b  = (const float*)d_in[2];   // biases  [4096]
    const float* nz = (const float*)d_in[3];   // noise   [4096,4096]
    float* out = (float*)d_out;

    const int qgrid = (NDIM * NDIM / 4) / 256;  // 16384
    quant_kernel<<<qgrid, 256>>>((const float4*)x, 0, 4.0f, 31.75f);
    quant_kernel<<<qgrid, 256>>>((const float4*)w, 1, 1.0f, 127.0f);
    quant_bias_kernel<<<NDIM / 256, 256>>>(b);

    cudaFuncSetAttribute(gemm_kernel, cudaFuncAttributeMaxDynamicSharedMemorySize, SMEM_TOTAL);
    dim3 grid(NDIM / BN, NDIM / BM);            // 32 x 32 = 1024 CTAs
    gemm_kernel<<<grid, 256, SMEM_TOTAL>>>(nz, out);
}

// round 5
// speedup vs baseline: 2.0493x; 1.5218x over previous
#include <cuda_runtime.h>
#include <cuda_bf16.h>
#include <stdint.h>

#define DI __device__ __forceinline__

// ---------------- problem constants ----------------
static constexpr int    NDIM     = 4096;
static constexpr float  INVSCALE = 1.0f / (31.75f * 127.0f);   // 1/(sx*sw)

// ---------------- GEMM tiling (bf16 HMMA) ----------------
static constexpr int BM = 256, BN = 128, BK = 64;
static constexpr int STAGES = 4;
static constexpr int KT = NDIM / BK;                    // 64 k-iterations
static constexpr int A_STAGE_B = BM * BK * 2;           // 32768
static constexpr int B_STAGE_B = BN * BK * 2;           // 16384
static constexpr int STAGE_B   = A_STAGE_B + B_STAGE_B; // 49152
static constexpr int SMEM_TOTAL = STAGES * STAGE_B;     // 196608

// ---------------- device scratch (allocation-free rule) ----------------
__device__ __nv_bfloat16 g_Xq[(size_t)NDIM * NDIM];   // quantized activations (integer-valued bf16)
__device__ __nv_bfloat16 g_Wq[(size_t)NDIM * NDIM];   // quantized weights (integer-valued bf16)
__device__ float         g_badd[NDIM];                // epilogue bias term

// ---------------- PTX helpers ----------------
DI uint32_t smem_u32(const void* p) {
    uint32_t a;
    asm("{ .reg .u64 t; cvta.to.shared.u64 t, %1; cvt.u32.u64 %0, t; }" : "=r"(a) : "l"(p));
    return a;
}
DI void cp16(uint32_t dst, const void* src) {
    asm volatile("cp.async.cg.shared.global [%0], [%1], 16;" :: "r"(dst), "l"(src) : "memory");
}
DI void cp_commit() { asm volatile("cp.async.commit_group;" ::: "memory"); }
template <int N> DI void cp_wait() { asm volatile("cp.async.wait_group %0;" :: "n"(N) : "memory"); }

DI void ldsm4(uint32_t* r, uint32_t addr) {
    asm volatile("ldmatrix.sync.aligned.m8n8.x4.shared.b16 {%0,%1,%2,%3}, [%4];"
                 : "=r"(r[0]), "=r"(r[1]), "=r"(r[2]), "=r"(r[3]) : "r"(addr));
}
DI void mma16816(float* c, const uint32_t* a, uint32_t b0, uint32_t b1) {
    asm volatile(
        "mma.sync.aligned.m16n8k16.row.col.f32.bf16.bf16.f32 "
        "{%0,%1,%2,%3}, {%4,%5,%6,%7}, {%8,%9}, {%0,%1,%2,%3};"
        : "+f"(c[0]), "+f"(c[1]), "+f"(c[2]), "+f"(c[3])
        : "r"(a[0]), "r"(a[1]), "r"(a[2]), "r"(a[3]), "r"(b0), "r"(b1));
}

// 128B-row swizzle: row = 128 bytes (64 bf16), chunk c in [0,8) 16B units
DI uint32_t sw_off(int row, int c) {
    return (uint32_t)(row * 128 + ((c ^ (row & 7)) << 4));
}

// ---------------- quantize kernels ----------------
__global__ void quant_kernel(const float4* __restrict__ src, int which,
                             float clip, float scale) {
    size_t i = (size_t)blockIdx.x * blockDim.x + threadIdx.x;
    float4 v = src[i];
    float a0 = rintf(fminf(clip, fmaxf(-clip, v.x)) * scale);
    float a1 = rintf(fminf(clip, fmaxf(-clip, v.y)) * scale);
    float a2 = rintf(fminf(clip, fmaxf(-clip, v.z)) * scale);
    float a3 = rintf(fminf(clip, fmaxf(-clip, v.w)) * scale);
    __nv_bfloat162 p0 = __floats2bfloat162_rn(a0, a1);
    __nv_bfloat162 p1 = __floats2bfloat162_rn(a2, a3);
    uint2 o;
    o.x = *reinterpret_cast<uint32_t*>(&p0);
    o.y = *reinterpret_cast<uint32_t*>(&p1);
    uint2* dst = reinterpret_cast<uint2*>(which ? g_Wq : g_Xq);
    dst[i] = o;
}

__global__ void quant_bias_kernel(const float* __restrict__ b) {
    int i = blockIdx.x * blockDim.x + threadIdx.x;
    float q = rintf(fminf(1.0f, fmaxf(-1.0f, b[i])) * 127.0f);
    g_badd[i] = 32.0f * q * INVSCALE;   // quantized ones-column (=32) * quantized bias
}

// ---------------- GEMM ----------------
DI void load_stage(const __nv_bfloat16* __restrict__ Ag,
                   const __nv_bfloat16* __restrict__ Bg,
                   uint32_t a_s, uint32_t b_s, int kc, int tid) {
    // A: 256 rows x 8 chunks (16B) = 2048; 256 threads x 8
#pragma unroll
    for (int j = 0; j < 8; ++j) {
        int idx = tid + j * 256;
        int row = idx >> 3, c = idx & 7;
        cp16(a_s + sw_off(row, c), Ag + ((size_t)row * NDIM + kc + c * 8));
    }
    // B: 128 rows x 8 chunks = 1024; 256 threads x 4
#pragma unroll
    for (int j = 0; j < 4; ++j) {
        int idx = tid + j * 256;
        int row = idx >> 3, c = idx & 7;
        cp16(b_s + sw_off(row, c), Bg + ((size_t)row * NDIM + kc + c * 8));
    }
}

__global__ __launch_bounds__(256, 1)
void gemm_kernel(const float* __restrict__ noise, float* __restrict__ out) {
    extern __shared__ __align__(1024) char smem[];
    const uint32_t smem_base = smem_u32(smem);
    const int tid  = threadIdx.x;
    const int lane = tid & 31;
    const int warp = tid >> 5;
    const int warpM = warp >> 1;     // 0..3, 64 rows each
    const int warpN = warp & 1;      // 0..1, 64 cols each

    const int tileM = blockIdx.y, tileN = blockIdx.x;
    const __nv_bfloat16* Ag = g_Xq + (size_t)tileM * BM * NDIM;
    const __nv_bfloat16* Bg = g_Wq + (size_t)tileN * BN * NDIM;

    float c[4][8][4];
#pragma unroll
    for (int i = 0; i < 4; ++i)
#pragma unroll
        for (int j = 0; j < 8; ++j)
#pragma unroll
            for (int k = 0; k < 4; ++k) c[i][j][k] = 0.0f;

    // per-lane swizzled ldmatrix base offsets (row += 16 just adds 2048 bytes)
    const int lrow = lane & 15;
    const int csel = lane >> 4;
    uint32_t offA0[4], offB0[4];   // [kk]
    {
        const int rA = warpM * 64 + lrow;
        const int rB = warpN * 64 + lrow;
#pragma unroll
        for (int kk = 0; kk < 4; ++kk) {
            offA0[kk] = sw_off(rA, (kk << 1) | csel);
            offB0[kk] = sw_off(rB, (kk << 1) | csel);
        }
    }

    // prologue: fill STAGES-1 stages
#pragma unroll
    for (int s = 0; s < STAGES - 1; ++s) {
        uint32_t a_s = smem_base + s * STAGE_B;
        load_stage(Ag, Bg, a_s, a_s + A_STAGE_B, s * BK, tid);
        cp_commit();
    }

    for (int kt = 0; kt < KT; ++kt) {
        cp_wait<STAGES - 2>();
        __syncthreads();
        const int s = kt & (STAGES - 1);
        const uint32_t a_s = smem_base + s * STAGE_B;
        const uint32_t b_s = a_s + A_STAGE_B;

        if (kt + STAGES - 1 < KT) {
            uint32_t na = smem_base + ((kt + STAGES - 1) & (STAGES - 1)) * STAGE_B;
            load_stage(Ag, Bg, na, na + A_STAGE_B, (kt + STAGES - 1) * BK, tid);
        }
        cp_commit();

#pragma unroll
        for (int kk = 0; kk < 4; ++kk) {
            uint32_t a[4][4], b[4][4];
#pragma unroll
            for (int h = 0; h < 4; ++h)
                ldsm4(a[h], a_s + offA0[kk] + (uint32_t)(h * 2048));
#pragma unroll
            for (int q = 0; q < 4; ++q)
                ldsm4(b[q], b_s + offB0[kk] + (uint32_t)(q * 2048));
#pragma unroll
            for (int h = 0; h < 4; ++h) {
#pragma unroll
                for (int q = 0; q < 4; ++q) {
                    mma16816(c[h][2 * q + 0], a[h], b[q][0], b[q][2]);
                    mma16816(c[h][2 * q + 1], a[h], b[q][1], b[q][3]);
                }
            }
        }
    }

    // ---- fused epilogue: out = acc*INV + badd[n] + 0.01*noise ----
    const int mBase = tileM * BM + warpM * 64 + (lane >> 2);
    const int nBase = tileN * BN + warpN * 64 + (lane & 3) * 2;
#pragma unroll
    for (int h = 0; h < 4; ++h) {
#pragma unroll
        for (int nt = 0; nt < 8; ++nt) {
#pragma unroll
            for (int half = 0; half < 2; ++half) {
                const int m = mBase + h * 16 + half * 8;
                const int n = nBase + nt * 8;
                const size_t off = (size_t)m * NDIM + n;
                float2 nz = *reinterpret_cast<const float2*>(noise + off);
                float2 bd = *reinterpret_cast<const float2*>(g_badd + n);
                float2 o;
                o.x = fmaf(c[h][nt][2 * half + 0], INVSCALE, fmaf(0.01f, nz.x, bd.x));
                o.y = fmaf(c[h][nt][2 * half + 1], INVSCALE, fmaf(0.01f, nz.y, bd.y));
                *reinterpret_cast<float2*>(out + off) = o;
            }
        }
    }
}

// ---------------- launch ----------------
extern "C" void kernel_launch(void* const* d_in, const int* in_sizes, int n_in,
                              void* d_out, int out_size) {
    const float* x  = (const float*)d_in[0];   // tensor  [4096,4096]
    const float* w  = (const float*)d_in[1];   // weights [4096,4096]
    const float* b  = (const float*)d_in[2];   // biases  [4096]
    const float* nz = (const float*)d_in[3];   // noise   [4096,4096]
    float* out = (float*)d_out;

    const int qgrid = (NDIM * NDIM / 4) / 256;  // 16384
    quant_kernel<<<qgrid, 256>>>((const float4*)x, 0, 4.0f, 31.75f);
    quant_kernel<<<qgrid, 256>>>((const float4*)w, 1, 1.0f, 127.0f);
    quant_bias_kernel<<<NDIM / 256, 256>>>(b);

    cudaFuncSetAttribute(gemm_kernel, cudaFuncAttributeMaxDynamicSharedMemorySize, SMEM_TOTAL);
    dim3 grid(NDIM / BN, NDIM / BM);            // 32 x 16 = 512 CTAs
    gemm_kernel<<<grid, 256, SMEM_TOTAL>>>(nz, out);
}

// round 6
// speedup vs baseline: 2.6584x; 1.2972x over previous
#include <cuda_runtime.h>
#include <cuda.h>
#include <cuda_bf16.h>
#include <stdint.h>

#define DI __device__ __forceinline__

// ---------------- problem constants ----------------
static constexpr int    NDIM     = 4096;
static constexpr float  INVSCALE = 1.0f / (31.75f * 127.0f);   // 1/(sx*sw)

// ---------------- GEMM tiling (bf16 HMMA + TMA) ----------------
static constexpr int BM = 128, BN = 128, BK = 64;
static constexpr int STAGES = 3;
static constexpr int KT = NDIM / BK;                    // 64 k-iterations
static constexpr int A_STAGE_B = BM * 128;              // 16384 (128 rows x 128B)
static constexpr int B_STAGE_B = BN * 128;              // 16384
static constexpr int STAGE_B   = A_STAGE_B + B_STAGE_B; // 32768
static constexpr int SMEM_HDR  = 1024;
static constexpr int SMEM_TOTAL = SMEM_HDR + STAGES * STAGE_B;  // 99328

// ---------------- device scratch (allocation-free rule) ----------------
__device__ __nv_bfloat16 g_Xq[(size_t)NDIM * NDIM];   // quantized activations (integer-valued bf16)
__device__ __nv_bfloat16 g_Wq[(size_t)NDIM * NDIM];   // quantized weights (integer-valued bf16)
__device__ float         g_badd[NDIM];                // epilogue bias term

// ---------------- PTX helpers ----------------
DI uint32_t smem_u32(const void* p) {
    uint32_t a;
    asm("{ .reg .u64 t; cvta.to.shared.u64 t, %1; cvt.u32.u64 %0, t; }" : "=r"(a) : "l"(p));
    return a;
}
DI void ldsm4(uint32_t* r, uint32_t addr) {
    asm volatile("ldmatrix.sync.aligned.m8n8.x4.shared.b16 {%0,%1,%2,%3}, [%4];"
                 : "=r"(r[0]), "=r"(r[1]), "=r"(r[2]), "=r"(r[3]) : "r"(addr));
}
DI void mma16816(float* c, const uint32_t* a, uint32_t b0, uint32_t b1) {
    asm volatile(
        "mma.sync.aligned.m16n8k16.row.col.f32.bf16.bf16.f32 "
        "{%0,%1,%2,%3}, {%4,%5,%6,%7}, {%8,%9}, {%0,%1,%2,%3};"
        : "+f"(c[0]), "+f"(c[1]), "+f"(c[2]), "+f"(c[3])
        : "r"(a[0]), "r"(a[1]), "r"(a[2]), "r"(a[3]), "r"(b0), "r"(b1));
}
// SW128 swizzled byte offset: 128B rows, 16B chunk c in [0,8)
DI uint32_t sw_off(int row, int c) {
    return (uint32_t)(row * 128 + ((c ^ (row & 7)) << 4));
}
DI void mbar_init(uint32_t a, uint32_t cnt) {
    asm volatile("mbarrier.init.shared.b64 [%0], %1;" :: "r"(a), "r"(cnt) : "memory");
}
DI void mbar_expect(uint32_t a, uint32_t bytes) {
    asm volatile("mbarrier.arrive.expect_tx.shared.b64 _, [%0], %1;"
                 :: "r"(a), "r"(bytes) : "memory");
}
DI void mbar_arrive(uint32_t a) {
    asm volatile("mbarrier.arrive.shared.b64 _, [%0];" :: "r"(a) : "memory");
}
DI void mbar_wait(uint32_t a, uint32_t parity) {
    asm volatile(
        "{\n\t.reg .pred P;\n"
        "WL_%=:\n\t"
        "mbarrier.try_wait.parity.acquire.cta.shared::cta.b64 P, [%0], %1, 0x989680;\n\t"
        "@P bra WD_%=;\n\t"
        "bra WL_%=;\n"
        "WD_%=:\n\t}"
        :: "r"(a), "r"(parity) : "memory");
}
DI void tma2d(uint32_t dst, const CUtensorMap* tm, int cx, int cy, uint32_t mbar) {
    asm volatile(
        "cp.async.bulk.tensor.2d.shared::cluster.global.tile.mbarrier::complete_tx::bytes "
        "[%0], [%1, {%2, %3}], [%4];"
        :: "r"(dst), "l"(tm), "r"(cx), "r"(cy), "r"(mbar) : "memory");
}

// ---------------- quantize kernels ----------------
__global__ void quant_kernel(const float4* __restrict__ src, int which,
                             float clip, float scale) {
    size_t i = (size_t)blockIdx.x * blockDim.x + threadIdx.x;
    float4 v = src[i];
    float a0 = rintf(fminf(clip, fmaxf(-clip, v.x)) * scale);
    float a1 = rintf(fminf(clip, fmaxf(-clip, v.y)) * scale);
    float a2 = rintf(fminf(clip, fmaxf(-clip, v.z)) * scale);
    float a3 = rintf(fminf(clip, fmaxf(-clip, v.w)) * scale);
    __nv_bfloat162 p0 = __floats2bfloat162_rn(a0, a1);
    __nv_bfloat162 p1 = __floats2bfloat162_rn(a2, a3);
    uint2 o;
    o.x = *reinterpret_cast<uint32_t*>(&p0);
    o.y = *reinterpret_cast<uint32_t*>(&p1);
    uint2* dst = reinterpret_cast<uint2*>(which ? g_Wq : g_Xq);
    dst[i] = o;
}

__global__ void quant_bias_kernel(const float* __restrict__ b) {
    int i = blockIdx.x * blockDim.x + threadIdx.x;
    float q = rintf(fminf(1.0f, fmaxf(-1.0f, b[i])) * 127.0f);
    g_badd[i] = 32.0f * q * INVSCALE;   // quantized ones-column (=32) * quantized bias
}

// ---------------- GEMM: TMA producer + HMMA consumers ----------------
__global__ __launch_bounds__(256, 2)
void gemm_kernel(const __grid_constant__ CUtensorMap tmA,
                 const __grid_constant__ CUtensorMap tmB,
                 const float* __restrict__ noise, float* __restrict__ out) {
    extern __shared__ __align__(1024) char smem[];
    const uint32_t sb = smem_u32(smem);
    const int tid  = threadIdx.x;
    const int lane = tid & 31;
    const int warp = tid >> 5;
    const int warpM = warp >> 1;     // 0..3, 32 rows each
    const int warpN = warp & 1;      // 0..1, 64 cols each

    const uint32_t FULL  = sb;       // full[s]  at sb + 8*s
    const uint32_t EMPTY = sb + 24;  // empty[s] at sb + 24 + 8*s

    if (tid == 0) {
#pragma unroll
        for (int s = 0; s < STAGES; ++s) {
            mbar_init(FULL + 8u * s, 1);
            mbar_init(EMPTY + 8u * s, 256);
        }
        asm volatile("fence.mbarrier_init.release.cluster;" ::: "memory");
    }
    __syncthreads();

    const int tileM = blockIdx.y, tileN = blockIdx.x;

    // prologue: fill all stages via TMA
    if (tid == 0) {
#pragma unroll
        for (int c = 0; c < STAGES; ++c) {
            const uint32_t a_s = sb + SMEM_HDR + c * STAGE_B;
            mbar_expect(FULL + 8u * c, (uint32_t)STAGE_B);
            tma2d(a_s,             &tmA, c * BK, tileM * BM, FULL + 8u * c);
            tma2d(a_s + A_STAGE_B, &tmB, c * BK, tileN * BN, FULL + 8u * c);
        }
    }

    float c[2][8][4];
#pragma unroll
    for (int i = 0; i < 2; ++i)
#pragma unroll
        for (int j = 0; j < 8; ++j)
#pragma unroll
            for (int k = 0; k < 4; ++k) c[i][j][k] = 0.0f;

    // per-lane swizzled ldmatrix base offsets (swizzle invariant under row+16 => +2048B)
    const int lrow = lane & 15;
    const int csel = lane >> 4;
    uint32_t offA0[4], offB0[4];
    {
        const int rA = warpM * 32 + lrow;
        const int rB = warpN * 64 + lrow;
#pragma unroll
        for (int kk = 0; kk < 4; ++kk) {
            offA0[kk] = sw_off(rA, (kk << 1) | csel);
            offB0[kk] = sw_off(rB, (kk << 1) | csel);
        }
    }

    int s = 0, ph = 0;
    for (int kt = 0; kt < KT; ++kt) {
        const uint32_t a_s = sb + SMEM_HDR + s * STAGE_B;
        const uint32_t b_s = a_s + A_STAGE_B;

        mbar_wait(FULL + 8u * s, (uint32_t)ph);

#pragma unroll
        for (int kk = 0; kk < 4; ++kk) {
            uint32_t a[2][4], b[4][4];
            ldsm4(a[0], a_s + offA0[kk]);
            ldsm4(a[1], a_s + offA0[kk] + 2048);
#pragma unroll
            for (int q = 0; q < 4; ++q)
                ldsm4(b[q], b_s + offB0[kk] + (uint32_t)(q * 2048));
#pragma unroll
            for (int q = 0; q < 4; ++q) {
                mma16816(c[0][2 * q + 0], a[0], b[q][0], b[q][2]);
                mma16816(c[0][2 * q + 1], a[0], b[q][1], b[q][3]);
                mma16816(c[1][2 * q + 0], a[1], b[q][0], b[q][2]);
                mma16816(c[1][2 * q + 1], a[1], b[q][1], b[q][3]);
            }
        }

        mbar_arrive(EMPTY + 8u * s);

        if (tid == 0 && kt + STAGES < KT) {
            // wait until ALL consumers released this slot, then refill it
            mbar_wait(EMPTY + 8u * s, (uint32_t)ph);
            mbar_expect(FULL + 8u * s, (uint32_t)STAGE_B);
            tma2d(a_s, &tmA, (kt + STAGES) * BK, tileM * BM, FULL + 8u * s);
            tma2d(b_s, &tmB, (kt + STAGES) * BK, tileN * BN, FULL + 8u * s);
        }

        if (++s == STAGES) { s = 0; ph ^= 1; }
    }

    // ---- fused epilogue: out = acc*INV + badd[n] + 0.01*noise ----
    const int mBase = tileM * BM + warpM * 32 + (lane >> 2);
    const int nBase = tileN * BN + warpN * 64 + (lane & 3) * 2;
#pragma unroll
    for (int mt = 0; mt < 2; ++mt) {
#pragma unroll
        for (int nt = 0; nt < 8; ++nt) {
#pragma unroll
            for (int half = 0; half < 2; ++half) {
                const int m = mBase + mt * 16 + half * 8;
                const int n = nBase + nt * 8;
                const size_t off = (size_t)m * NDIM + n;
                float2 nz = *reinterpret_cast<const float2*>(noise + off);
                float2 bd = *reinterpret_cast<const float2*>(g_badd + n);
                float2 o;
                o.x = fmaf(c[mt][nt][2 * half + 0], INVSCALE, fmaf(0.01f, nz.x, bd.x));
                o.y = fmaf(c[mt][nt][2 * half + 1], INVSCALE, fmaf(0.01f, nz.y, bd.y));
                *reinterpret_cast<float2*>(out + off) = o;
            }
        }
    }
}

// ---------------- launch ----------------
typedef CUresult (*PFN_tmEncode)(
    CUtensorMap*, CUtensorMapDataType, cuuint32_t, void*,
    const cuuint64_t*, const cuuint64_t*, const cuuint32_t*, const cuuint32_t*,
    CUtensorMapInterleave, CUtensorMapSwizzle, CUtensorMapL2promotion,
    CUtensorMapFloatOOBfill);

extern "C" void kernel_launch(void* const* d_in, const int* in_sizes, int n_in,
                              void* d_out, int out_size) {
    const float* x  = (const float*)d_in[0];   // tensor  [4096,4096]
    const float* w  = (const float*)d_in[1];   // weights [4096,4096]
    const float* b  = (const float*)d_in[2];   // biases  [4096]
    const float* nz = (const float*)d_in[3];   // noise   [4096,4096]
    float* out = (float*)d_out;

    const int qgrid = (NDIM * NDIM / 4) / 256;  // 16384
    quant_kernel<<<qgrid, 256>>>((const float4*)x, 0, 4.0f, 31.75f);
    quant_kernel<<<qgrid, 256>>>((const float4*)w, 1, 1.0f, 127.0f);
    quant_bias_kernel<<<NDIM / 256, 256>>>(b);

    // build tensormaps (host-side, pure; no allocation)
    void* encFn = nullptr;
    cudaDriverEntryPointQueryResult qres;
    cudaGetDriverEntryPoint("cuTensorMapEncodeTiled", &encFn, cudaEnableDefault, &qres);
    PFN_tmEncode enc = (PFN_tmEncode)encFn;

    void *xq_ptr = nullptr, *wq_ptr = nullptr;
    cudaGetSymbolAddress(&xq_ptr, g_Xq);
    cudaGetSymbolAddress(&wq_ptr, g_Wq);

    cuuint64_t dims[2]    = {(cuuint64_t)NDIM, (cuuint64_t)NDIM};
    cuuint64_t strides[1] = {(cuuint64_t)NDIM * 2};
    cuuint32_t box[2]     = {(cuuint32_t)BK, (cuuint32_t)BM};   // 64 elems x 128 rows
    cuuint32_t estr[2]    = {1, 1};

    CUtensorMap tmA, tmB;
    enc(&tmA, CU_TENSOR_MAP_DATA_TYPE_BFLOAT16, 2, xq_ptr, dims, strides, box, estr,
        CU_TENSOR_MAP_INTERLEAVE_NONE, CU_TENSOR_MAP_SWIZZLE_128B,
        CU_TENSOR_MAP_L2_PROMOTION_L2_128B, CU_TENSOR_MAP_FLOAT_OOB_FILL_NONE);
    enc(&tmB, CU_TENSOR_MAP_DATA_TYPE_BFLOAT16, 2, wq_ptr, dims, strides, box, estr,
        CU_TENSOR_MAP_INTERLEAVE_NONE, CU_TENSOR_MAP_SWIZZLE_128B,
        CU_TENSOR_MAP_L2_PROMOTION_L2_128B, CU_TENSOR_MAP_FLOAT_OOB_FILL_NONE);

    cudaFuncSetAttribute(gemm_kernel, cudaFuncAttributeMaxDynamicSharedMemorySize, SMEM_TOTAL);
    dim3 grid(NDIM / BN, NDIM / BM);            // 32 x 32 = 1024 CTAs
    gemm_kernel<<<grid, 256, SMEM_TOTAL>>>(tmA, tmB, nz, out);
}

// round 7
// speedup vs baseline: 2.7247x; 1.0249x over previous
#include <cuda_runtime.h>
#include <cuda.h>
#include <cuda_bf16.h>
#include <stdint.h>

#define DI __device__ __forceinline__

// ---------------- problem constants ----------------
static constexpr int    NDIM     = 4096;
static constexpr float  INVSCALE = 1.0f / (31.75f * 127.0f);   // 1/(sx*sw)

// ---------------- GEMM tiling (bf16 HMMA + TMA, warp-specialized) ----------------
static constexpr int BM = 128, BN = 128, BK = 64;
static constexpr int STAGES = 3;
static constexpr int KT = NDIM / BK;                    // 64 k-iterations
static constexpr int A_STAGE_B = BM * 128;              // 16384 (128 rows x 128B)
static constexpr int B_STAGE_B = BN * 128;              // 16384
static constexpr int STAGE_B   = A_STAGE_B + B_STAGE_B; // 32768
static constexpr int SMEM_HDR  = 1024;
static constexpr int SMEM_TOTAL = SMEM_HDR + STAGES * STAGE_B;  // 99328
static constexpr int NCONS = 256;                       // consumer threads

// ---------------- device scratch (allocation-free rule) ----------------
__device__ __nv_bfloat16 g_Xq[(size_t)NDIM * NDIM];   // quantized activations (integer-valued bf16)
__device__ __nv_bfloat16 g_Wq[(size_t)NDIM * NDIM];   // quantized weights (integer-valued bf16)
__device__ float         g_badd[NDIM];                // epilogue bias term

// ---------------- PTX helpers ----------------
DI uint32_t smem_u32(const void* p) {
    uint32_t a;
    asm("{ .reg .u64 t; cvta.to.shared.u64 t, %1; cvt.u32.u64 %0, t; }" : "=r"(a) : "l"(p));
    return a;
}
DI void ldsm4(uint32_t* r, uint32_t addr) {
    asm volatile("ldmatrix.sync.aligned.m8n8.x4.shared.b16 {%0,%1,%2,%3}, [%4];"
                 : "=r"(r[0]), "=r"(r[1]), "=r"(r[2]), "=r"(r[3]) : "r"(addr));
}
DI void mma16816(float* c, const uint32_t* a, uint32_t b0, uint32_t b1) {
    asm volatile(
        "mma.sync.aligned.m16n8k16.row.col.f32.bf16.bf16.f32 "
        "{%0,%1,%2,%3}, {%4,%5,%6,%7}, {%8,%9}, {%0,%1,%2,%3};"
        : "+f"(c[0]), "+f"(c[1]), "+f"(c[2]), "+f"(c[3])
        : "r"(a[0]), "r"(a[1]), "r"(a[2]), "r"(a[3]), "r"(b0), "r"(b1));
}
// SW128 swizzled byte offset: 128B rows, 16B chunk c in [0,8)
DI uint32_t sw_off(int row, int c) {
    return (uint32_t)(row * 128 + ((c ^ (row & 7)) << 4));
}
DI void mbar_init(uint32_t a, uint32_t cnt) {
    asm volatile("mbarrier.init.shared.b64 [%0], %1;" :: "r"(a), "r"(cnt) : "memory");
}
DI void mbar_expect(uint32_t a, uint32_t bytes) {
    asm volatile("mbarrier.arrive.expect_tx.shared.b64 _, [%0], %1;"
                 :: "r"(a), "r"(bytes) : "memory");
}
DI void mbar_arrive(uint32_t a) {
    asm volatile("mbarrier.arrive.shared.b64 _, [%0];" :: "r"(a) : "memory");
}
DI void mbar_wait(uint32_t a, uint32_t parity) {
    asm volatile(
        "{\n\t.reg .pred P;\n"
        "WL_%=:\n\t"
        "mbarrier.try_wait.parity.acquire.cta.shared::cta.b64 P, [%0], %1, 0x989680;\n\t"
        "@P bra WD_%=;\n\t"
        "bra WL_%=;\n"
        "WD_%=:\n\t}"
        :: "r"(a), "r"(parity) : "memory");
}
DI void tma2d(uint32_t dst, const CUtensorMap* tm, int cx, int cy, uint32_t mbar) {
    asm volatile(
        "cp.async.bulk.tensor.2d.shared::cluster.global.tile.mbarrier::complete_tx::bytes "
        "[%0], [%1, {%2, %3}], [%4];"
        :: "r"(dst), "l"(tm), "r"(cx), "r"(cy), "r"(mbar) : "memory");
}

// ---------------- quantize kernels ----------------
__global__ void quant_kernel(const float4* __restrict__ src, int which,
                             float clip, float scale) {
    size_t i = (size_t)blockIdx.x * blockDim.x + threadIdx.x;
    float4 v = src[i];
    float a0 = rintf(fminf(clip, fmaxf(-clip, v.x)) * scale);
    float a1 = rintf(fminf(clip, fmaxf(-clip, v.y)) * scale);
    float a2 = rintf(fminf(clip, fmaxf(-clip, v.z)) * scale);
    float a3 = rintf(fminf(clip, fmaxf(-clip, v.w)) * scale);
    __nv_bfloat162 p0 = __floats2bfloat162_rn(a0, a1);
    __nv_bfloat162 p1 = __floats2bfloat162_rn(a2, a3);
    uint2 o;
    o.x = *reinterpret_cast<uint32_t*>(&p0);
    o.y = *reinterpret_cast<uint32_t*>(&p1);
    uint2* dst = reinterpret_cast<uint2*>(which ? g_Wq : g_Xq);
    dst[i] = o;
}

__global__ void quant_bias_kernel(const float* __restrict__ b) {
    int i = blockIdx.x * blockDim.x + threadIdx.x;
    float q = rintf(fminf(1.0f, fmaxf(-1.0f, b[i])) * 127.0f);
    g_badd[i] = 32.0f * q * INVSCALE;   // quantized ones-column (=32) * quantized bias
}

// ---------------- GEMM: producer warp (TMA) + 8 consumer warps (HMMA) ----------------
__global__ __launch_bounds__(288, 2)
void gemm_kernel(const __grid_constant__ CUtensorMap tmA,
                 const __grid_constant__ CUtensorMap tmB,
                 const float* __restrict__ noise, float* __restrict__ out) {
    extern __shared__ __align__(1024) char smem[];
    const uint32_t sb = smem_u32(smem);
    const int tid  = threadIdx.x;
    const int lane = tid & 31;

    const uint32_t FULL  = sb;       // full[s]  at sb + 8*s
    const uint32_t EMPTY = sb + 24;  // empty[s] at sb + 24 + 8*s

    if (tid == 0) {
#pragma unroll
        for (int s = 0; s < STAGES; ++s) {
            mbar_init(FULL + 8u * s, 1);
            mbar_init(EMPTY + 8u * s, NCONS);
        }
        asm volatile("fence.mbarrier_init.release.cluster;" ::: "memory");
    }
    __syncthreads();

    const int tileM = blockIdx.y, tileN = blockIdx.x;

    if (tid >= NCONS) {
        // ================= producer warp (lane 0 only) =================
        if (lane == 0) {
#pragma unroll
            for (int f = 0; f < STAGES; ++f) {
                const uint32_t a_s = sb + SMEM_HDR + f * STAGE_B;
                mbar_expect(FULL + 8u * f, (uint32_t)STAGE_B);
                tma2d(a_s,             &tmA, f * BK, tileM * BM, FULL + 8u * f);
                tma2d(a_s + A_STAGE_B, &tmB, f * BK, tileN * BN, FULL + 8u * f);
            }
            int s = 0, php = 0;
            for (int f = STAGES; f < KT; ++f) {
                const uint32_t a_s = sb + SMEM_HDR + s * STAGE_B;
                mbar_wait(EMPTY + 8u * s, (uint32_t)php);
                mbar_expect(FULL + 8u * s, (uint32_t)STAGE_B);
                tma2d(a_s,             &tmA, f * BK, tileM * BM, FULL + 8u * s);
                tma2d(a_s + A_STAGE_B, &tmB, f * BK, tileN * BN, FULL + 8u * s);
                if (++s == STAGES) { s = 0; php ^= 1; }
            }
        }
        return;
    }

    // ================= consumer warps =================
    const int warp  = tid >> 5;
    const int warpM = warp >> 1;     // 0..3, 32 rows each
    const int warpN = warp & 1;      // 0..1, 64 cols each

    float c[2][8][4];
#pragma unroll
    for (int i = 0; i < 2; ++i)
#pragma unroll
        for (int j = 0; j < 8; ++j)
#pragma unroll
            for (int k = 0; k < 4; ++k) c[i][j][k] = 0.0f;

    // per-lane swizzled ldmatrix base offsets (swizzle invariant under row+16 => +2048B)
    const int lrow = lane & 15;
    const int csel = lane >> 4;
    uint32_t offA0[4], offB0[4];
    {
        const int rA = warpM * 32 + lrow;
        const int rB = warpN * 64 + lrow;
#pragma unroll
        for (int kk = 0; kk < 4; ++kk) {
            offA0[kk] = sw_off(rA, (kk << 1) | csel);
            offB0[kk] = sw_off(rB, (kk << 1) | csel);
        }
    }

    int s = 0, ph = 0;
    for (int kt = 0; kt < KT; ++kt) {
        const uint32_t a_s = sb + SMEM_HDR + s * STAGE_B;
        const uint32_t b_s = a_s + A_STAGE_B;

        mbar_wait(FULL + 8u * s, (uint32_t)ph);

#pragma unroll
        for (int kk = 0; kk < 4; ++kk) {
            uint32_t a[2][4], b[4][4];
            ldsm4(a[0], a_s + offA0[kk]);
            ldsm4(a[1], a_s + offA0[kk] + 2048);
#pragma unroll
            for (int q = 0; q < 4; ++q)
                ldsm4(b[q], b_s + offB0[kk] + (uint32_t)(q * 2048));
#pragma unroll
            for (int q = 0; q < 4; ++q) {
                mma16816(c[0][2 * q + 0], a[0], b[q][0], b[q][2]);
                mma16816(c[0][2 * q + 1], a[0], b[q][1], b[q][3]);
                mma16816(c[1][2 * q + 0], a[1], b[q][0], b[q][2]);
                mma16816(c[1][2 * q + 1], a[1], b[q][1], b[q][3]);
            }
        }

        mbar_arrive(EMPTY + 8u * s);
        if (++s == STAGES) { s = 0; ph ^= 1; }
    }

    // ---- fused epilogue: out = acc*INV + badd[n] + 0.01*noise ----
    const int mBase = tileM * BM + warpM * 32 + (lane >> 2);
    const int nBase = tileN * BN + warpN * 64 + (lane & 3) * 2;
#pragma unroll
    for (int mt = 0; mt < 2; ++mt) {
#pragma unroll
        for (int nt = 0; nt < 8; ++nt) {
#pragma unroll
            for (int half = 0; half < 2; ++half) {
                const int m = mBase + mt * 16 + half * 8;
                const int n = nBase + nt * 8;
                const size_t off = (size_t)m * NDIM + n;
                float2 nz = *reinterpret_cast<const float2*>(noise + off);
                float2 bd = *reinterpret_cast<const float2*>(g_badd + n);
                float2 o;
                o.x = fmaf(c[mt][nt][2 * half + 0], INVSCALE, fmaf(0.01f, nz.x, bd.x));
                o.y = fmaf(c[mt][nt][2 * half + 1], INVSCALE, fmaf(0.01f, nz.y, bd.y));
                *reinterpret_cast<float2*>(out + off) = o;
            }
        }
    }
}

// ---------------- launch ----------------
typedef CUresult (*PFN_tmEncode)(
    CUtensorMap*, CUtensorMapDataType, cuuint32_t, void*,
    const cuuint64_t*, const cuuint64_t*, const cuuint32_t*, const cuuint32_t*,
    CUtensorMapInterleave, CUtensorMapSwizzle, CUtensorMapL2promotion,
    CUtensorMapFloatOOBfill);

extern "C" void kernel_launch(void* const* d_in, const int* in_sizes, int n_in,
                              void* d_out, int out_size) {
    const float* x  = (const float*)d_in[0];   // tensor  [4096,4096]
    const float* w  = (const float*)d_in[1];   // weights [4096,4096]
    const float* b  = (const float*)d_in[2];   // biases  [4096]
    const float* nz = (const float*)d_in[3];   // noise   [4096,4096]
    float* out = (float*)d_out;

    const int qgrid = (NDIM * NDIM / 4) / 256;  // 16384
    quant_kernel<<<qgrid, 256>>>((const float4*)x, 0, 4.0f, 31.75f);
    quant_kernel<<<qgrid, 256>>>((const float4*)w, 1, 1.0f, 127.0f);
    quant_bias_kernel<<<NDIM / 256, 256>>>(b);

    // build tensormaps (host-side, pure; no allocation)
    void* encFn = nullptr;
    cudaDriverEntryPointQueryResult qres;
    cudaGetDriverEntryPoint("cuTensorMapEncodeTiled", &encFn, cudaEnableDefault, &qres);
    PFN_tmEncode enc = (PFN_tmEncode)encFn;

    void *xq_ptr = nullptr, *wq_ptr = nullptr;
    cudaGetSymbolAddress(&xq_ptr, g_Xq);
    cudaGetSymbolAddress(&wq_ptr, g_Wq);

    cuuint64_t dims[2]    = {(cuuint64_t)NDIM, (cuuint64_t)NDIM};
    cuuint64_t strides[1] = {(cuuint64_t)NDIM * 2};
    cuuint32_t box[2]     = {(cuuint32_t)BK, (cuuint32_t)BM};   // 64 elems x 128 rows
    cuuint32_t estr[2]    = {1, 1};

    CUtensorMap tmA, tmB;
    enc(&tmA, CU_TENSOR_MAP_DATA_TYPE_BFLOAT16, 2, xq_ptr, dims, strides, box, estr,
        CU_TENSOR_MAP_INTERLEAVE_NONE, CU_TENSOR_MAP_SWIZZLE_128B,
        CU_TENSOR_MAP_L2_PROMOTION_L2_128B, CU_TENSOR_MAP_FLOAT_OOB_FILL_NONE);
    enc(&tmB, CU_TENSOR_MAP_DATA_TYPE_BFLOAT16, 2, wq_ptr, dims, strides, box, estr,
        CU_TENSOR_MAP_INTERLEAVE_NONE, CU_TENSOR_MAP_SWIZZLE_128B,
        CU_TENSOR_MAP_L2_PROMOTION_L2_128B, CU_TENSOR_MAP_FLOAT_OOB_FILL_NONE);

    cudaFuncSetAttribute(gemm_kernel, cudaFuncAttributeMaxDynamicSharedMemorySize, SMEM_TOTAL);
    dim3 grid(NDIM / BN, NDIM / BM);            // 32 x 32 = 1024 CTAs
    gemm_kernel<<<grid, 288, SMEM_TOTAL>>>(tmA, tmB, nz, out);
}